// round 14
// baseline (speedup 1.0000x reference)
#include <cuda_runtime.h>

// Global accumulators: [0]=pos_loss, [1]=neg_loss, [2]=pos_count, [3]=neg_count
// Zero at module load; last finishing block resets them after writing d_out,
// so every graph replay starts from identical state.
__device__ double g_acc[4];
__device__ unsigned int g_ticket;

// Per-element focal-neg term; accumulates unscaled nll*w and w.
__device__ __forceinline__ void neg_elem(float x, float p, float& lL, float& lW)
{
    const float e   = __expf(x);
    const float t   = 1.0f + e;
    const float s   = __fdividef(e, t);      // sigmoid(x)
    const float nll = __logf(t);             // softplus(x) = -log_sigmoid(-x)
    const float w   = (p == -1.0f) ? s * s : 0.0f;
    lL = fmaf(nll, w, lL);
    lW += w;
}

__device__ __forceinline__ void neg_quad(const float4 x4, const float4 p4,
                                         float& lL, float& lW)
{
    neg_elem(x4.x, p4.x, lL, lW);
    neg_elem(x4.y, p4.y, lL, lW);
    neg_elem(x4.z, p4.z, lL, lW);
    neg_elem(x4.w, p4.w, lL, lW);
}

// One level, software-pipelined: prefetch round n+1's 4 LDG.128 before
// computing round n, so the memory stream stays busy during the MUFU grind.
__device__ __forceinline__ void neg_level(const float4* __restrict__ L,
                                          const float4* __restrict__ P,
                                          int nv, int gtid, int stride,
                                          float& lL, float& lW)
{
    const int step = 2 * stride;
    int i = gtid;

    if (i + stride < nv) {
        float4 a0 = L[i];
        float4 p0 = P[i];
        float4 a1 = L[i + stride];
        float4 p1 = P[i + stride];
        int inext = i + step;

        while (inext + stride < nv) {
            // prefetch next round (4 independent LDG.128 in flight during compute)
            const float4 b0 = L[inext];
            const float4 q0 = P[inext];
            const float4 b1 = L[inext + stride];
            const float4 q1 = P[inext + stride];

            neg_quad(a0, p0, lL, lW);
            neg_quad(a1, p1, lL, lW);

            a0 = b0; p0 = q0; a1 = b1; p1 = q1;
            inext += step;
        }
        neg_quad(a0, p0, lL, lW);
        neg_quad(a1, p1, lL, lW);
        i = inext;
    }
    for (; i < nv; i += stride) {
        neg_quad(L[i], P[i], lL, lW);
    }
}

// ---------------------------------------------------------------------------
// Fused kernel: pos branch (768 points spread one-warp-per-point across
// blocks) + neg branch (pipelined per-level loops) + last-block finalize.
// ---------------------------------------------------------------------------
__global__ void __launch_bounds__(256, 4)
fused_kernel(const float*  __restrict__ lgf0,
             const float*  __restrict__ lgf1,
             const float*  __restrict__ lgf2,
             const int*    __restrict__ co0,
             const int*    __restrict__ co1,
             const int*    __restrict__ co2,
             const float4* __restrict__ pr0,
             const float4* __restrict__ pr1,
             const float4* __restrict__ pr2,
             int n0v, int n1v, int n2v,
             float* __restrict__ out)
{
    const int warp = threadIdx.x >> 5;
    const int lane = threadIdx.x & 31;

    // =====================  POS branch (768 points)  =====================
    // Spread: point index = warp * gridDim + blockIdx -> at most
    // ceil(768/gridDim)=2 pos warps per block (gridDim >= 384).
    const int ppoint = warp * gridDim.x + blockIdx.x;
    if (ppoint < 768) {
        int lvl, rem;
        if (ppoint < 256)      { lvl = 0; rem = ppoint; }
        else if (ppoint < 512) { lvl = 1; rem = ppoint - 256; }
        else                   { lvl = 2; rem = ppoint - 512; }
        const int b = rem >> 7;
        const int p = rem & 127;

        const float* lg;
        const int*   co;
        int D;
        float factor;
        if (lvl == 0)      { lg = lgf0; co = co0; D = 128; factor = 4.0f; }
        else if (lvl == 1) { lg = lgf1; co = co1; D = 64;  factor = 2.0f; }
        else               { lg = lgf2; co = co2; D = 32;  factor = 1.0f; }

        const int r = lvl + 1;
        const int n = 2 * r;
        const int nwin = n * n * n;        // 8 / 64 / 216

        const int base = (b * 128 + p) * 4;
        const int a = co[base + 0];
        const int y = co[base + 1];
        const int x = co[base + 2];
        const int z = co[base + 3];

        const float valid = (a > -1) ? 1.0f : 0.0f;
        const int ac = min(max(a, 0), 1);
        const int yc = min(max(y, 0), D - 1);
        const int xc = min(max(x, 0), D - 1);
        const int zc = min(max(z, 0), D - 1);

        const long long plane = ((long long)(b * 2 + ac)) * D * D * D;

        float wmax = -3.4e38f;
        for (int idx = lane; idx < nwin; idx += 32) {
            const int j = idx / (n * n);
            const int k = (idx / n) % n;
            const int l = idx % n;
            const int iy = min(max(yc - r + j, 0), D - 1);
            const int ix = min(max(xc - r + k, 0), D - 1);
            const int iz = min(max(zc - r + l, 0), D - 1);
            const float v = lg[plane + ((long long)iy * D + ix) * D + iz];
            wmax = fmaxf(wmax, v);
        }
        #pragma unroll
        for (int off = 16; off > 0; off >>= 1)
            wmax = fmaxf(wmax, __shfl_xor_sync(0xFFFFFFFFu, wmax, off));

        if (lane == 0) {
            const float point = lg[plane + ((long long)yc * D + xc) * D + zc];
            const bool near_low = (yc < r) || (xc < r) || (zc < r);
            const float lp = near_low ? point : wmax;

            float sig, logsig;
            if (lp >= 0.0f) {
                const float e = expf(-lp);
                sig    = 1.0f / (1.0f + e);
                logsig = -log1pf(e);
            } else {
                const float e = expf(lp);
                sig    = e / (1.0f + e);
                logsig = lp - log1pf(e);
            }
            const float om = 1.0f - sig;
            const float w  = om * om * valid;
            const float loss = -logsig * w * factor;

            atomicAdd(&g_acc[0], (double)loss);
            atomicAdd(&g_acc[2], (double)w);
        }
    }

    // =====================  NEG branch: per-level pipelined loops  ==========
    const int gtid   = blockIdx.x * blockDim.x + threadIdx.x;
    const int stride = gridDim.x * blockDim.x;

    float sL = 0.0f, sW = 0.0f;
    {
        float lL = 0.0f, lW = 0.0f;
        neg_level((const float4*)lgf0, pr0, n0v, gtid, stride, lL, lW);
        sL = fmaf(lL, 4.0f, sL);  sW += lW;
    }
    {
        float lL = 0.0f, lW = 0.0f;
        neg_level((const float4*)lgf1, pr1, n1v, gtid, stride, lL, lW);
        sL = fmaf(lL, 2.0f, sL);  sW += lW;
    }
    {
        float lL = 0.0f, lW = 0.0f;
        neg_level((const float4*)lgf2, pr2, n2v, gtid, stride, lL, lW);
        sL += lL;  sW += lW;
    }

    // block reduction of neg partials
    #pragma unroll
    for (int off = 16; off > 0; off >>= 1) {
        sL += __shfl_xor_sync(0xFFFFFFFFu, sL, off);
        sW += __shfl_xor_sync(0xFFFFFFFFu, sW, off);
    }
    __shared__ float shL[8], shW[8];
    if (lane == 0) { shL[warp] = sL; shW[warp] = sW; }
    __syncthreads();
    if (warp == 0) {
        float vL = (lane < 8) ? shL[lane] : 0.0f;
        float vW = (lane < 8) ? shW[lane] : 0.0f;
        #pragma unroll
        for (int off = 4; off > 0; off >>= 1) {
            vL += __shfl_xor_sync(0xFFFFFFFFu, vL, off);
            vW += __shfl_xor_sync(0xFFFFFFFFu, vW, off);
        }
        if (lane == 0) {
            atomicAdd(&g_acc[1], (double)vL);
            atomicAdd(&g_acc[3], (double)vW);
        }
    }
    __syncthreads();

    // =====================  last-block finalize  =====================
    if (threadIdx.x == 0) {
        __threadfence();
        const unsigned rank = atomicAdd(&g_ticket, 1u);
        if (rank == gridDim.x - 1) {
            __threadfence();
            volatile double* acc = g_acc;
            out[0] = (float)acc[0];
            out[1] = (float)acc[1];
            out[2] = (float)acc[2];
            out[3] = (float)acc[3];
            g_acc[0] = 0.0; g_acc[1] = 0.0; g_acc[2] = 0.0; g_acc[3] = 0.0;
            g_ticket = 0u;
        }
    }
}

extern "C" void kernel_launch(void* const* d_in, const int* in_sizes, int n_in,
                              void* d_out, int out_size)
{
    // Resolve inputs generically by element count (order-independent):
    // three distinct large float sizes (desc) = levels 0/1/2; within a level
    // logits appears before prob; small int buffers are coord0..2 in order.
    int lvl_size[3] = {0, 0, 0};
    for (int i = 0; i < n_in; ++i) {
        const int sz = in_sizes[i];
        if (sz <= 4096) continue;
        bool seen = false;
        for (int k = 0; k < 3; ++k) if (lvl_size[k] == sz) { seen = true; break; }
        if (seen) continue;
        for (int k = 0; k < 3; ++k) {
            if (sz > lvl_size[k]) {
                for (int m = 2; m > k; --m) lvl_size[m] = lvl_size[m - 1];
                lvl_size[k] = sz;
                break;
            }
        }
    }

    const float* lg[3] = {nullptr, nullptr, nullptr};
    const float* pr[3] = {nullptr, nullptr, nullptr};
    const int*   co[3] = {nullptr, nullptr, nullptr};
    int n_coord = 0;

    for (int i = 0; i < n_in; ++i) {
        const int sz = in_sizes[i];
        if (sz <= 4096) {
            if (n_coord < 3) co[n_coord++] = (const int*)d_in[i];
            continue;
        }
        int lvl = -1;
        for (int k = 0; k < 3; ++k) if (sz == lvl_size[k]) { lvl = k; break; }
        if (lvl < 0) continue;
        if (lg[lvl] == nullptr)      lg[lvl] = (const float*)d_in[i];
        else if (pr[lvl] == nullptr) pr[lvl] = (const float*)d_in[i];
    }

    if (!lg[0] || !lg[1] || !lg[2] || !pr[0] || !pr[1] || !pr[2] ||
        !co[0] || !co[1] || !co[2]) {
        return;  // should not happen for this problem
    }

    const int n0v = lvl_size[0] / 4;
    const int n1v = lvl_size[1] / 4;
    const int n2v = lvl_size[2] / 4;

    const int threads = 256;
    // One full wave at 4 blocks/SM (forced by __launch_bounds__(256,4)):
    // 148 SMs * 4 = 592 blocks.
    const int blocks = 592;

    fused_kernel<<<blocks, threads>>>(lg[0], lg[1], lg[2],
                                      co[0], co[1], co[2],
                                      (const float4*)pr[0],
                                      (const float4*)pr[1],
                                      (const float4*)pr[2],
                                      n0v, n1v, n2v,
                                      (float*)d_out);
}

// round 15
// speedup vs baseline: 1.0660x; 1.0660x over previous
#include <cuda_runtime.h>

// Global accumulators: [0]=pos_loss, [1]=neg_loss, [2]=pos_count, [3]=neg_count
// Zero at module load; last finishing block resets them after writing d_out,
// so every graph replay starts from identical state.
__device__ double g_acc[4];
__device__ unsigned int g_ticket;

// Per-element focal-neg term; accumulates unscaled nll*w and w.
__device__ __forceinline__ void neg_elem(float x, float p, float& lL, float& lW)
{
    const float e   = __expf(x);
    const float t   = 1.0f + e;
    const float s   = __fdividef(e, t);      // sigmoid(x)
    const float nll = __logf(t);             // softplus(x) = -log_sigmoid(-x)
    const float w   = (p == -1.0f) ? s * s : 0.0f;
    lL = fmaf(nll, w, lL);
    lW += w;
}

__device__ __forceinline__ void neg_quad(const float4 x4, const float4 p4,
                                         float& lL, float& lW)
{
    neg_elem(x4.x, p4.x, lL, lW);
    neg_elem(x4.y, p4.y, lL, lW);
    neg_elem(x4.z, p4.z, lL, lW);
    neg_elem(x4.w, p4.w, lL, lW);
}

// One level: grid-stride, 3x unrolled. Loads batched at loop head
// (6 independent LDG.128 in flight), streaming (evict-first) since the
// data is touched exactly once.
__device__ __forceinline__ void neg_level(const float4* __restrict__ L,
                                          const float4* __restrict__ P,
                                          int nv, int gtid, int stride,
                                          float& lL, float& lW)
{
    int i = gtid;
    for (; i + 2 * stride < nv; i += 3 * stride) {
        const float4 a0 = __ldcs(L + i);
        const float4 p0 = __ldcs(P + i);
        const float4 a1 = __ldcs(L + i + stride);
        const float4 p1 = __ldcs(P + i + stride);
        const float4 a2 = __ldcs(L + i + 2 * stride);
        const float4 p2 = __ldcs(P + i + 2 * stride);
        neg_quad(a0, p0, lL, lW);
        neg_quad(a1, p1, lL, lW);
        neg_quad(a2, p2, lL, lW);
    }
    for (; i < nv; i += stride) {
        const float4 a = __ldcs(L + i);
        const float4 p = __ldcs(P + i);
        neg_quad(a, p, lL, lW);
    }
}

// ---------------------------------------------------------------------------
// Fused kernel: pos branch (768 points, spread <=1 warp/block) +
// neg branch (per-level 3x-unrolled streaming loops) + last-block finalize.
// ---------------------------------------------------------------------------
__global__ void __launch_bounds__(256, 6)
fused_kernel(const float*  __restrict__ lgf0,
             const float*  __restrict__ lgf1,
             const float*  __restrict__ lgf2,
             const int*    __restrict__ co0,
             const int*    __restrict__ co1,
             const int*    __restrict__ co2,
             const float4* __restrict__ pr0,
             const float4* __restrict__ pr1,
             const float4* __restrict__ pr2,
             int n0v, int n1v, int n2v,
             float* __restrict__ out)
{
    const int warp = threadIdx.x >> 5;
    const int lane = threadIdx.x & 31;

    // =====================  POS branch (768 points)  =====================
    // Spread: point = warp * gridDim + blockIdx -> <=1 pos warp per block
    // for gridDim >= 768.
    const int ppoint = warp * gridDim.x + blockIdx.x;
    if (ppoint < 768) {
        int lvl, rem;
        if (ppoint < 256)      { lvl = 0; rem = ppoint; }
        else if (ppoint < 512) { lvl = 1; rem = ppoint - 256; }
        else                   { lvl = 2; rem = ppoint - 512; }
        const int b = rem >> 7;
        const int p = rem & 127;

        const float* lg;
        const int*   co;
        int D;
        float factor;
        if (lvl == 0)      { lg = lgf0; co = co0; D = 128; factor = 4.0f; }
        else if (lvl == 1) { lg = lgf1; co = co1; D = 64;  factor = 2.0f; }
        else               { lg = lgf2; co = co2; D = 32;  factor = 1.0f; }

        const int r = lvl + 1;
        const int n = 2 * r;
        const int nwin = n * n * n;        // 8 / 64 / 216

        const int base = (b * 128 + p) * 4;
        const int a = co[base + 0];
        const int y = co[base + 1];
        const int x = co[base + 2];
        const int z = co[base + 3];

        const float valid = (a > -1) ? 1.0f : 0.0f;
        const int ac = min(max(a, 0), 1);
        const int yc = min(max(y, 0), D - 1);
        const int xc = min(max(x, 0), D - 1);
        const int zc = min(max(z, 0), D - 1);

        const long long plane = ((long long)(b * 2 + ac)) * D * D * D;

        float wmax = -3.4e38f;
        for (int idx = lane; idx < nwin; idx += 32) {
            const int j = idx / (n * n);
            const int k = (idx / n) % n;
            const int l = idx % n;
            const int iy = min(max(yc - r + j, 0), D - 1);
            const int ix = min(max(xc - r + k, 0), D - 1);
            const int iz = min(max(zc - r + l, 0), D - 1);
            const float v = lg[plane + ((long long)iy * D + ix) * D + iz];
            wmax = fmaxf(wmax, v);
        }
        #pragma unroll
        for (int off = 16; off > 0; off >>= 1)
            wmax = fmaxf(wmax, __shfl_xor_sync(0xFFFFFFFFu, wmax, off));

        if (lane == 0) {
            const float point = lg[plane + ((long long)yc * D + xc) * D + zc];
            const bool near_low = (yc < r) || (xc < r) || (zc < r);
            const float lp = near_low ? point : wmax;

            float sig, logsig;
            if (lp >= 0.0f) {
                const float e = expf(-lp);
                sig    = 1.0f / (1.0f + e);
                logsig = -log1pf(e);
            } else {
                const float e = expf(lp);
                sig    = e / (1.0f + e);
                logsig = lp - log1pf(e);
            }
            const float om = 1.0f - sig;
            const float w  = om * om * valid;
            const float loss = -logsig * w * factor;

            atomicAdd(&g_acc[0], (double)loss);
            atomicAdd(&g_acc[2], (double)w);
        }
    }

    // =====================  NEG branch: per-level loops  =====================
    const int gtid   = blockIdx.x * blockDim.x + threadIdx.x;
    const int stride = gridDim.x * blockDim.x;

    float sL = 0.0f, sW = 0.0f;
    {
        float lL = 0.0f, lW = 0.0f;
        neg_level((const float4*)lgf0, pr0, n0v, gtid, stride, lL, lW);
        sL = fmaf(lL, 4.0f, sL);  sW += lW;
    }
    {
        float lL = 0.0f, lW = 0.0f;
        neg_level((const float4*)lgf1, pr1, n1v, gtid, stride, lL, lW);
        sL = fmaf(lL, 2.0f, sL);  sW += lW;
    }
    {
        float lL = 0.0f, lW = 0.0f;
        neg_level((const float4*)lgf2, pr2, n2v, gtid, stride, lL, lW);
        sL += lL;  sW += lW;
    }

    // block reduction of neg partials
    #pragma unroll
    for (int off = 16; off > 0; off >>= 1) {
        sL += __shfl_xor_sync(0xFFFFFFFFu, sL, off);
        sW += __shfl_xor_sync(0xFFFFFFFFu, sW, off);
    }
    __shared__ float shL[8], shW[8];
    if (lane == 0) { shL[warp] = sL; shW[warp] = sW; }
    __syncthreads();
    if (warp == 0) {
        float vL = (lane < 8) ? shL[lane] : 0.0f;
        float vW = (lane < 8) ? shW[lane] : 0.0f;
        #pragma unroll
        for (int off = 4; off > 0; off >>= 1) {
            vL += __shfl_xor_sync(0xFFFFFFFFu, vL, off);
            vW += __shfl_xor_sync(0xFFFFFFFFu, vW, off);
        }
        if (lane == 0) {
            atomicAdd(&g_acc[1], (double)vL);
            atomicAdd(&g_acc[3], (double)vW);
        }
    }
    __syncthreads();

    // =====================  last-block finalize  =====================
    if (threadIdx.x == 0) {
        __threadfence();
        const unsigned rank = atomicAdd(&g_ticket, 1u);
        if (rank == gridDim.x - 1) {
            __threadfence();
            volatile double* acc = g_acc;
            out[0] = (float)acc[0];
            out[1] = (float)acc[1];
            out[2] = (float)acc[2];
            out[3] = (float)acc[3];
            g_acc[0] = 0.0; g_acc[1] = 0.0; g_acc[2] = 0.0; g_acc[3] = 0.0;
            g_ticket = 0u;
        }
    }
}

extern "C" void kernel_launch(void* const* d_in, const int* in_sizes, int n_in,
                              void* d_out, int out_size)
{
    // Resolve inputs generically by element count (order-independent):
    // three distinct large float sizes (desc) = levels 0/1/2; within a level
    // logits appears before prob; small int buffers are coord0..2 in order.
    int lvl_size[3] = {0, 0, 0};
    for (int i = 0; i < n_in; ++i) {
        const int sz = in_sizes[i];
        if (sz <= 4096) continue;
        bool seen = false;
        for (int k = 0; k < 3; ++k) if (lvl_size[k] == sz) { seen = true; break; }
        if (seen) continue;
        for (int k = 0; k < 3; ++k) {
            if (sz > lvl_size[k]) {
                for (int m = 2; m > k; --m) lvl_size[m] = lvl_size[m - 1];
                lvl_size[k] = sz;
                break;
            }
        }
    }

    const float* lg[3] = {nullptr, nullptr, nullptr};
    const float* pr[3] = {nullptr, nullptr, nullptr};
    const int*   co[3] = {nullptr, nullptr, nullptr};
    int n_coord = 0;

    for (int i = 0; i < n_in; ++i) {
        const int sz = in_sizes[i];
        if (sz <= 4096) {
            if (n_coord < 3) co[n_coord++] = (const int*)d_in[i];
            continue;
        }
        int lvl = -1;
        for (int k = 0; k < 3; ++k) if (sz == lvl_size[k]) { lvl = k; break; }
        if (lvl < 0) continue;
        if (lg[lvl] == nullptr)      lg[lvl] = (const float*)d_in[i];
        else if (pr[lvl] == nullptr) pr[lvl] = (const float*)d_in[i];
    }

    if (!lg[0] || !lg[1] || !lg[2] || !pr[0] || !pr[1] || !pr[2] ||
        !co[0] || !co[1] || !co[2]) {
        return;  // should not happen for this problem
    }

    const int n0v = lvl_size[0] / 4;
    const int n1v = lvl_size[1] / 4;
    const int n2v = lvl_size[2] / 4;

    const int threads = 256;
    // One full wave at 6 blocks/SM (forced by __launch_bounds__(256,6)):
    // 148 SMs * 6 = 888 blocks.
    const int blocks = 888;

    fused_kernel<<<blocks, threads>>>(lg[0], lg[1], lg[2],
                                      co[0], co[1], co[2],
                                      (const float4*)pr[0],
                                      (const float4*)pr[1],
                                      (const float4*)pr[2],
                                      n0v, n1v, n2v,
                                      (float*)d_out);
}